// round 2
// baseline (speedup 1.0000x reference)
#include <cuda_runtime.h>
#include <math.h>
#include <stdint.h>

#define T_FRAMES 2048
#define EPROJS   1024
#define DUNITS   512
#define JOINT    512
#define ODIM     10000
#define NB       148
#define NT       512

// ---------------- global scratch (sanctioned __device__ arrays) ----------------
__device__ float    g_hp[T_FRAMES * JOINT];   // 4 MB encoder-side joint projection
__device__ float    g_y[DUNITS];
__device__ float    g_z[JOINT];
__device__ float    g_pm[NB];                 // per-block partial max
__device__ int      g_pa[NB];                 // per-block partial argmax (global row)
__device__ float    g_ps[NB];                 // per-block partial sum exp(l - pm)
__device__ unsigned g_bar;                    // grid barrier counter

__global__ void init_kernel() { g_bar = 0u; }

// ---------------- hp = h @ W_enc^T + b_enc  (2048 x 512, K=1024) ----------------
// grid 256 blocks x 256 threads, 8 t-rows per block, warp computes 4 j at a time.
__global__ void hp_kernel(const float* __restrict__ h,
                          const float* __restrict__ Wenc,
                          const float* __restrict__ benc) {
    __shared__ float sh[8 * EPROJS];
    const int tid  = threadIdx.x;
    const int warp = tid >> 5;
    const int lane = tid & 31;
    const size_t t0 = (size_t)blockIdx.x * 8;

    const float4* hsrc = (const float4*)(h + t0 * EPROJS);
    float4* sh4 = (float4*)sh;
    for (int i = tid; i < 8 * EPROJS / 4; i += 256) sh4[i] = hsrc[i];
    __syncthreads();

    const float4* w0 = (const float4*)Wenc;  // rows of length 1024 -> 256 float4
    for (int pass = 0; pass < 16; pass++) {
        int jb = (pass * 8 + warp) * 4;      // 4 consecutive j's
        float acc[8][4];
#pragma unroll
        for (int tt = 0; tt < 8; tt++)
#pragma unroll
            for (int jj = 0; jj < 4; jj++) acc[tt][jj] = 0.f;

        for (int qq = 0; qq < 8; qq++) {
            int q = qq * 32 + lane;          // coalesced across lanes
            float4 w[4];
#pragma unroll
            for (int jj = 0; jj < 4; jj++)
                w[jj] = w0[(size_t)(jb + jj) * (EPROJS / 4) + q];
#pragma unroll
            for (int tt = 0; tt < 8; tt++) {
                float4 hv = sh4[tt * (EPROJS / 4) + q];
#pragma unroll
                for (int jj = 0; jj < 4; jj++)
                    acc[tt][jj] += hv.x * w[jj].x + hv.y * w[jj].y +
                                   hv.z * w[jj].z + hv.w * w[jj].w;
            }
        }
#pragma unroll
        for (int tt = 0; tt < 8; tt++) {
#pragma unroll
            for (int jj = 0; jj < 4; jj++) {
                float v = acc[tt][jj];
                for (int off = 16; off; off >>= 1)
                    v += __shfl_down_sync(0xffffffffu, v, off);
                if (lane == 0)
                    g_hp[(t0 + tt) * JOINT + jb + jj] = v + benc[jb + jj];
            }
        }
    }
}

// ---------------- persistent decode kernel ----------------
__device__ __forceinline__ float sigm(float x) { return 1.f / (1.f + expf(-x)); }

// smem layout (floats)
#define SM_WOUT   0
#define SM_WHH    (SM_WOUT + 68 * JOINT)          // 34816
#define SM_WIH    (SM_WHH + 16 * DUNITS)          // +8192
#define SM_WDEC   (SM_WIH + 16 * DUNITS)          // +8192
#define SM_Y      (SM_WDEC + 4 * DUNITS)          // +2048
#define SM_Z      (SM_Y + DUNITS)
#define SM_EY     (SM_Z + JOINT)
#define SM_LOGIT  (SM_EY + DUNITS)                // 96
#define SM_BOUT   (SM_LOGIT + 96)                 // 96
#define SM_GH     (SM_BOUT + 96)                  // 16
#define SM_GATE   (SM_GH + 16)                    // 16
#define SM_BIAS   (SM_GATE + 16)                  // 16
#define SM_C      (SM_BIAS + 16)                  // 4
#define SM_BC     (SM_C + 4)                      // 4
#define SM_TOTAL_FLOATS (SM_BC + 8)

__global__ void __launch_bounds__(NT, 1)
decode_kernel(const float* __restrict__ embed,
              const float* __restrict__ Wih, const float* __restrict__ Whh,
              const float* __restrict__ bih, const float* __restrict__ bhh,
              const float* __restrict__ Wdec, const float* __restrict__ Wout,
              const float* __restrict__ bout,
              float* __restrict__ out, int out_size) {
    extern __shared__ float sm[];
    const int b    = blockIdx.x;
    const int tid  = threadIdx.x;
    const int warp = tid >> 5;
    const int lane = tid & 31;

    const int r0 = (b * ODIM) / NB, r1 = ((b + 1) * ODIM) / NB, nr = r1 - r0;
    const int k0 = (b * DUNITS) / NB, k1 = ((b + 1) * DUNITS) / NB, nk = k1 - k0;

    float* sWout = sm + SM_WOUT;
    float* sWhh  = sm + SM_WHH;
    float* sWih  = sm + SM_WIH;
    float* sWdec = sm + SM_WDEC;
    float* s_y   = sm + SM_Y;
    float* s_z   = sm + SM_Z;
    float* s_ey  = sm + SM_EY;
    float* s_lg  = sm + SM_LOGIT;
    float* s_bo  = sm + SM_BOUT;
    float* s_gh  = sm + SM_GH;
    float* s_gt  = sm + SM_GATE;
    float* s_bs  = sm + SM_BIAS;
    float* s_c   = sm + SM_C;
    float* s_bc  = sm + SM_BC;

    // ---- load weights into shared (resident for entire decode) ----
    {
        const float4* src = (const float4*)(Wout + (size_t)r0 * JOINT);
        float4* dst = (float4*)sWout;
        for (int i = tid; i < nr * (JOINT / 4); i += NT) dst[i] = src[i];
    }
    for (int i = tid; i < nr; i += NT) s_bo[i] = bout[r0 + i];
    {
        const int ng = 4 * nk;
        for (int i = tid; i < ng * (DUNITS / 4); i += NT) {
            int lr = i / (DUNITS / 4), x = i % (DUNITS / 4);
            int gi = lr & 3, ki = lr >> 2;
            size_t G = (size_t)(gi * DUNITS + k0 + ki);
            ((float4*)sWhh)[i] = ((const float4*)(Whh + G * DUNITS))[x];
            ((float4*)sWih)[i] = ((const float4*)(Wih + G * DUNITS))[x];
        }
        for (int i = tid; i < ng; i += NT) {
            int gi = i & 3, ki = i >> 2;
            int G = gi * DUNITS + k0 + ki;
            s_bs[i] = bih[G] + bhh[G];
        }
    }
    {
        const float4* src = (const float4*)(Wdec + (size_t)k0 * DUNITS);
        float4* dst = (float4*)sWdec;
        for (int i = tid; i < nk * (DUNITS / 4); i += NT) dst[i] = src[i];
    }
    __syncthreads();

    // ---- initial prediction-net step: zero input, zero state -> gates = biases
    if (tid < nk) {
        float gi_ = s_bs[tid * 4 + 0], gf_ = s_bs[tid * 4 + 1];
        float gg_ = s_bs[tid * 4 + 2], go_ = s_bs[tid * 4 + 3];
        (void)gf_;
        float c = sigm(gi_) * tanhf(gg_);    // f-gate * 0 drops out
        float yv = sigm(go_) * tanhf(c);
        s_c[tid] = c;
        g_y[k0 + tid] = yv;
    }

    unsigned bar_target = 0;
    float score = 0.f;

#define GRID_BARRIER()                                                   \
    do {                                                                 \
        __syncthreads();                                                 \
        if (tid == 0) {                                                  \
            __threadfence();                                             \
            atomicAdd(&g_bar, 1u);                                       \
            bar_target += NB;                                            \
            while (*(volatile unsigned*)&g_bar < bar_target)             \
                __nanosleep(32);                                         \
            __threadfence();                                             \
        }                                                                \
        __syncthreads();                                                 \
    } while (0)

    GRID_BARRIER();   // y0 visible everywhere

    for (int t = 0; t < T_FRAMES; t++) {
        // ======== phase 1: z = tanh(hp_t + W_dec*y) rows, gh = W_hh*y rows ====
        for (int i = tid; i < DUNITS / 4; i += NT)
            ((float4*)s_y)[i] = ((const float4*)g_y)[i];
        __syncthreads();

        const int witems = 5 * nk;   // nk z-rows + 4*nk gh-rows
        for (int it = warp; it < witems; it += (NT / 32)) {
            bool isz = it < nk;
            const float4* rp4 = (const float4*)(isz ? (sWdec + it * DUNITS)
                                                    : (sWhh + (it - nk) * DUNITS));
            const float4* y4 = (const float4*)s_y;
            float acc = 0.f;
#pragma unroll 4
            for (int q = lane; q < DUNITS / 4; q += 32) {
                float4 w = rp4[q], yv = y4[q];
                acc += w.x * yv.x + w.y * yv.y + w.z * yv.z + w.w * yv.w;
            }
            for (int off = 16; off; off >>= 1)
                acc += __shfl_down_sync(0xffffffffu, acc, off);
            if (lane == 0) {
                if (isz) {
                    float zv = tanhf(g_hp[(size_t)t * JOINT + k0 + it] + acc);
                    g_z[k0 + it] = zv;
                } else {
                    s_gh[it - nk] = acc;
                }
            }
        }
        GRID_BARRIER();

        // ======== phase 2: logits chunk, partial max/argmax/sumexp ============
        for (int i = tid; i < JOINT / 4; i += NT)
            ((float4*)s_z)[i] = ((const float4*)g_z)[i];
        __syncthreads();

        for (int lr = warp; lr < nr; lr += (NT / 32)) {
            const float4* rp4 = (const float4*)(sWout + lr * JOINT);
            const float4* z4 = (const float4*)s_z;
            float acc = 0.f;
#pragma unroll 4
            for (int q = lane; q < JOINT / 4; q += 32) {
                float4 w = rp4[q], zv = z4[q];
                acc += w.x * zv.x + w.y * zv.y + w.z * zv.z + w.w * zv.w;
            }
            for (int off = 16; off; off >>= 1)
                acc += __shfl_down_sync(0xffffffffu, acc, off);
            if (lane == 0) s_lg[lr] = acc + s_bo[lr];
        }
        __syncthreads();

        if (warp == 0) {
            float m = -INFINITY; int a = 0x7fffffff;
            for (int i = lane; i < nr; i += 32) {
                float v = s_lg[i]; int gidx = r0 + i;
                if (v > m || (v == m && gidx < a)) { m = v; a = gidx; }
            }
            for (int off = 16; off; off >>= 1) {
                float m2 = __shfl_down_sync(0xffffffffu, m, off);
                int   a2 = __shfl_down_sync(0xffffffffu, a, off);
                if (m2 > m || (m2 == m && a2 < a)) { m = m2; a = a2; }
            }
            m = __shfl_sync(0xffffffffu, m, 0);
            a = __shfl_sync(0xffffffffu, a, 0);
            float s = 0.f;
            for (int i = lane; i < nr; i += 32) s += expf(s_lg[i] - m);
            for (int off = 16; off; off >>= 1)
                s += __shfl_down_sync(0xffffffffu, s, off);
            if (lane == 0) { g_pm[b] = m; g_pa[b] = a; g_ps[b] = s; }
        }
        GRID_BARRIER();

        // ======== phase 3: redundant global reduce + LSTM update ==============
        if (warp == 0) {
            float m = -INFINITY; int a = 0x7fffffff;
            for (int i = lane; i < NB; i += 32) {
                float v = g_pm[i]; int ai = g_pa[i];
                if (v > m || (v == m && ai < a)) { m = v; a = ai; }
            }
            for (int off = 16; off; off >>= 1) {
                float m2 = __shfl_down_sync(0xffffffffu, m, off);
                int   a2 = __shfl_down_sync(0xffffffffu, a, off);
                if (m2 > m || (m2 == m && a2 < a)) { m = m2; a = a2; }
            }
            m = __shfl_sync(0xffffffffu, m, 0);
            a = __shfl_sync(0xffffffffu, a, 0);
            float s = 0.f;
            for (int i = lane; i < NB; i += 32)
                s += g_ps[i] * expf(g_pm[i] - m);
            for (int off = 16; off; off >>= 1)
                s += __shfl_down_sync(0xffffffffu, s, off);
            if (lane == 0) {
                s_bc[0] = __int_as_float(a);
                s_bc[1] = -logf(s);
            }
        }
        __syncthreads();

        const int   pred    = __float_as_int(s_bc[0]);
        const float logp    = s_bc[1];
        const bool  emitted = (pred != 0);

        if (b == 0 && tid == 0) {
            if (t < out_size) out[t] = emitted ? (float)pred : 0.0f;
            if (emitted) score += logp;
        }

        if (emitted) {
            for (int i = tid; i < DUNITS / 4; i += NT)
                ((float4*)s_ey)[i] = ((const float4*)(embed + (size_t)pred * DUNITS))[i];
            __syncthreads();

            for (int lr = warp; lr < 4 * nk; lr += (NT / 32)) {
                const float4* rp4 = (const float4*)(sWih + lr * DUNITS);
                const float4* e4 = (const float4*)s_ey;
                float acc = 0.f;
#pragma unroll 4
                for (int q = lane; q < DUNITS / 4; q += 32) {
                    float4 w = rp4[q], ev = e4[q];
                    acc += w.x * ev.x + w.y * ev.y + w.z * ev.z + w.w * ev.w;
                }
                for (int off = 16; off; off >>= 1)
                    acc += __shfl_down_sync(0xffffffffu, acc, off);
                if (lane == 0) s_gt[lr] = s_bs[lr] + s_gh[lr] + acc;
            }
            __syncthreads();

            if (tid < nk) {
                float gi_ = s_gt[tid * 4 + 0], gf_ = s_gt[tid * 4 + 1];
                float gg_ = s_gt[tid * 4 + 2], go_ = s_gt[tid * 4 + 3];
                float c  = s_c[tid];
                float cn = sigm(gf_) * c + sigm(gi_) * tanhf(gg_);
                float yn = sigm(go_) * tanhf(cn);
                s_c[tid] = cn;
                g_y[k0 + tid] = yn;
            }
        }
        GRID_BARRIER();   // y update visible for next step
    }

    if (b == 0) {
        if (tid == 0 && out_size > T_FRAMES) out[T_FRAMES] = score;
        for (int i = T_FRAMES + 1 + tid; i < out_size; i += NT) out[i] = 0.f;
    }
#undef GRID_BARRIER
}

// ---------------- launch ----------------
extern "C" void kernel_launch(void* const* d_in, const int* in_sizes, int n_in,
                              void* d_out, int out_size) {
    (void)in_sizes; (void)n_in;
    const float* h     = (const float*)d_in[0];
    const float* embed = (const float*)d_in[1];
    const float* Wih   = (const float*)d_in[2];
    const float* Whh   = (const float*)d_in[3];
    const float* bih   = (const float*)d_in[4];
    const float* bhh   = (const float*)d_in[5];
    const float* Wenc  = (const float*)d_in[6];
    const float* benc  = (const float*)d_in[7];
    const float* Wdec  = (const float*)d_in[8];
    const float* Wout  = (const float*)d_in[9];
    const float* bout  = (const float*)d_in[10];
    float* out = (float*)d_out;

    const int smem_bytes = SM_TOTAL_FLOATS * (int)sizeof(float);
    cudaFuncSetAttribute(decode_kernel,
                         cudaFuncAttributeMaxDynamicSharedMemorySize, smem_bytes);

    init_kernel<<<1, 1>>>();
    hp_kernel<<<T_FRAMES / 8, 256>>>(h, Wenc, benc);
    decode_kernel<<<NB, NT, smem_bytes>>>(embed, Wih, Whh, bih, bhh,
                                          Wdec, Wout, bout, out, out_size);
}

// round 3
// speedup vs baseline: 1.0678x; 1.0678x over previous
#include <cuda_runtime.h>
#include <math.h>
#include <stdint.h>

#define T_FRAMES 2048
#define EPROJS   1024
#define DUNITS   512
#define JOINT    512
#define ODIM     10000
#define NB       148
#define NT       512
#define NWARP    (NT / 32)

// ---------------- global scratch ----------------
__device__ float g_hp[T_FRAMES * JOINT];      // encoder-side joint projection
__device__ float g_y[2][DUNITS];              // double-buffered prediction-net state
__device__ float g_z[2][JOINT];               // double-buffered joint hidden
__device__ float g_pm[2][NB];                 // per-block partial max
__device__ int   g_pa[2][NB];                 // per-block partial argmax
__device__ float g_ps[2][NB];                 // per-block partial sumexp
__device__ __align__(128) unsigned g_cy;      // y-element arrivals (512/step)
__device__ __align__(128) unsigned g_cz;      // z-row arrivals (512/step)
__device__ __align__(128) unsigned g_cp;      // partial-triple arrivals (148/step)

__device__ __forceinline__ void red_release(unsigned* p) {
    asm volatile("red.release.gpu.global.add.u32 [%0], 1;" :: "l"(p) : "memory");
}
__device__ __forceinline__ unsigned ld_acquire(unsigned* p) {
    unsigned v;
    asm volatile("ld.acquire.gpu.global.u32 %0, [%1];" : "=r"(v) : "l"(p) : "memory");
    return v;
}
__device__ __forceinline__ float sigm(float x) { return 1.f / (1.f + expf(-x)); }

// ---------------- hp = h @ W_enc^T + b_enc ----------------
__global__ void hp_kernel(const float* __restrict__ h,
                          const float* __restrict__ Wenc,
                          const float* __restrict__ benc) {
    if (blockIdx.x == 0 && threadIdx.x == 0) { g_cy = 0u; g_cz = 0u; g_cp = 0u; }

    __shared__ float sh[8 * EPROJS];
    const int tid  = threadIdx.x;
    const int warp = tid >> 5;
    const int lane = tid & 31;
    const size_t t0 = (size_t)blockIdx.x * 8;

    const float4* hsrc = (const float4*)(h + t0 * EPROJS);
    float4* sh4 = (float4*)sh;
    for (int i = tid; i < 8 * EPROJS / 4; i += 256) sh4[i] = hsrc[i];
    __syncthreads();

    const float4* w0 = (const float4*)Wenc;
    for (int pass = 0; pass < 16; pass++) {
        int jb = (pass * 8 + warp) * 4;
        float acc[8][4];
#pragma unroll
        for (int tt = 0; tt < 8; tt++)
#pragma unroll
            for (int jj = 0; jj < 4; jj++) acc[tt][jj] = 0.f;

        for (int qq = 0; qq < 8; qq++) {
            int q = qq * 32 + lane;
            float4 w[4];
#pragma unroll
            for (int jj = 0; jj < 4; jj++)
                w[jj] = w0[(size_t)(jb + jj) * (EPROJS / 4) + q];
#pragma unroll
            for (int tt = 0; tt < 8; tt++) {
                float4 hv = sh4[tt * (EPROJS / 4) + q];
#pragma unroll
                for (int jj = 0; jj < 4; jj++)
                    acc[tt][jj] += hv.x * w[jj].x + hv.y * w[jj].y +
                                   hv.z * w[jj].z + hv.w * w[jj].w;
            }
        }
#pragma unroll
        for (int tt = 0; tt < 8; tt++) {
#pragma unroll
            for (int jj = 0; jj < 4; jj++) {
                float v = acc[tt][jj];
                for (int off = 16; off; off >>= 1)
                    v += __shfl_down_sync(0xffffffffu, v, off);
                if (lane == 0)
                    g_hp[(t0 + tt) * JOINT + jb + jj] = v + benc[jb + jj];
            }
        }
    }
}

// ---------------- smem layout (floats) ----------------
#define SM_WOUT   0
#define SM_WHH    (SM_WOUT + 68 * JOINT)
#define SM_WIH    (SM_WHH + 16 * DUNITS)
#define SM_WDEC   (SM_WIH + 16 * DUNITS)
#define SM_Y      (SM_WDEC + 4 * DUNITS)
#define SM_Z      (SM_Y + DUNITS)
#define SM_EY     (SM_Z + JOINT)
#define SM_BO     (SM_EY + DUNITS)
#define SM_GH     (SM_BO + 96)
#define SM_GT     (SM_GH + 16)
#define SM_BS     (SM_GT + 16)
#define SM_C      (SM_BS + 16)
#define SM_MY     (SM_C + 4)
#define SM_BC     (SM_MY + 4)
#define SM_WM     (SM_BC + 8)
#define SM_WA     (SM_WM + NWARP)
#define SM_WS     (SM_WA + NWARP)
#define SM_TOTAL_FLOATS (SM_WS + NWARP)

__global__ void __launch_bounds__(NT, 1)
decode_kernel(const float* __restrict__ embed,
              const float* __restrict__ Wih, const float* __restrict__ Whh,
              const float* __restrict__ bih, const float* __restrict__ bhh,
              const float* __restrict__ Wdec, const float* __restrict__ Wout,
              const float* __restrict__ bout,
              float* __restrict__ out, int out_size) {
    extern __shared__ float sm[];
    const int b    = blockIdx.x;
    const int tid  = threadIdx.x;
    const int warp = tid >> 5;
    const int lane = tid & 31;

    const int r0 = (b * ODIM) / NB, r1 = ((b + 1) * ODIM) / NB, nr = r1 - r0;
    const int k0 = (b * DUNITS) / NB, k1 = ((b + 1) * DUNITS) / NB, nk = k1 - k0;

    float* sWout = sm + SM_WOUT;
    float* sWhh  = sm + SM_WHH;
    float* sWih  = sm + SM_WIH;
    float* sWdec = sm + SM_WDEC;
    float* s_y   = sm + SM_Y;
    float* s_z   = sm + SM_Z;
    float* s_ey  = sm + SM_EY;
    float* s_bo  = sm + SM_BO;
    float* s_gh  = sm + SM_GH;
    float* s_gt  = sm + SM_GT;
    float* s_bs  = sm + SM_BS;
    float* s_c   = sm + SM_C;
    float* s_my  = sm + SM_MY;
    float* s_bc  = sm + SM_BC;
    float* s_wm  = sm + SM_WM;
    int*   s_wa  = (int*)(sm + SM_WA);
    float* s_ws  = sm + SM_WS;

    // ---- load weights into shared (resident for entire decode) ----
    {
        const float4* src = (const float4*)(Wout + (size_t)r0 * JOINT);
        float4* dst = (float4*)sWout;
        for (int i = tid; i < nr * (JOINT / 4); i += NT) dst[i] = src[i];
    }
    for (int i = tid; i < nr; i += NT) s_bo[i] = bout[r0 + i];
    {
        const int ng = 4 * nk;
        for (int i = tid; i < ng * (DUNITS / 4); i += NT) {
            int lr = i / (DUNITS / 4), x = i % (DUNITS / 4);
            int gi = lr & 3, ki = lr >> 2;
            size_t G = (size_t)(gi * DUNITS + k0 + ki);
            ((float4*)sWhh)[i] = ((const float4*)(Whh + G * DUNITS))[x];
            ((float4*)sWih)[i] = ((const float4*)(Wih + G * DUNITS))[x];
        }
        for (int i = tid; i < ng; i += NT) {
            int gi = i & 3, ki = i >> 2;
            int G = gi * DUNITS + k0 + ki;
            s_bs[i] = bih[G] + bhh[G];
        }
    }
    {
        const float4* src = (const float4*)(Wdec + (size_t)k0 * DUNITS);
        float4* dst = (float4*)sWdec;
        for (int i = tid; i < nk * (DUNITS / 4); i += NT) dst[i] = src[i];
    }
    __syncthreads();

    // ---- prologue: y0 from zero input / zero state (gates = biases) ----
    if (tid < nk) {
        float gi_ = s_bs[4 * tid + 0];
        float gg_ = s_bs[4 * tid + 2];
        float go_ = s_bs[4 * tid + 3];
        float c  = sigm(gi_) * tanhf(gg_);
        float yv = sigm(go_) * tanhf(c);
        s_c[tid]  = c;
        s_my[tid] = yv;
        g_y[0][k0 + tid] = yv;
        red_release(&g_cy);
    }

    float score = 0.f;

    for (int t = 0; t < T_FRAMES; t++) {
        const int par = t & 1;

        // ===== wait y(t), stage =====
        if (tid == 0) {
            unsigned tgt = (unsigned)DUNITS * (unsigned)(t + 1);
            while (ld_acquire(&g_cy) < tgt) {}
        }
        __syncthreads();
        if (tid < DUNITS / 4)
            ((float4*)s_y)[tid] = __ldcv(((const float4*)g_y[par]) + tid);
        __syncthreads();

        // ===== z rows (publish ASAP), then gh rows (overlap) =====
        for (int it = warp; it < 5 * nk; it += NWARP) {
            const float4* r4 = (const float4*)((it < nk)
                                ? (sWdec + it * DUNITS)
                                : (sWhh + (it - nk) * DUNITS));
            const float4* y4 = (const float4*)s_y;
            float acc = 0.f;
#pragma unroll
            for (int q = 0; q < 4; q++) {
                float4 w = r4[lane + 32 * q], yv = y4[lane + 32 * q];
                acc += w.x * yv.x + w.y * yv.y + w.z * yv.z + w.w * yv.w;
            }
            for (int off = 16; off; off >>= 1)
                acc += __shfl_down_sync(0xffffffffu, acc, off);
            if (lane == 0) {
                if (it < nk) {
                    float zv = tanhf(__ldg(&g_hp[(size_t)t * JOINT + k0 + it]) + acc);
                    g_z[par][k0 + it] = zv;
                    red_release(&g_cz);
                } else {
                    s_gh[it - nk] = acc;
                }
            }
        }

        // ===== wait z(t), stage to regs =====
        if (tid == 0) {
            unsigned tgt = (unsigned)JOINT * (unsigned)(t + 1);
            while (ld_acquire(&g_cz) < tgt) {}
        }
        __syncthreads();
        if (tid < JOINT / 4)
            ((float4*)s_z)[tid] = __ldcv(((const float4*)g_z[par]) + tid);
        __syncthreads();

        float4 zr[4];
#pragma unroll
        for (int q = 0; q < 4; q++) zr[q] = ((const float4*)s_z)[lane + 32 * q];

        // ===== logits rows: batched dots, batched shuffle reduces =====
        float accv[5];
        int rcount = 0;
        for (int lr = warp, i = 0; lr < nr; lr += NWARP, i++) {
            const float4* r4 = (const float4*)(sWout + lr * JOINT);
            float a = 0.f;
#pragma unroll
            for (int q = 0; q < 4; q++) {
                float4 w = r4[lane + 32 * q];
                a += w.x * zr[q].x + w.y * zr[q].y + w.z * zr[q].z + w.w * zr[q].w;
            }
            accv[i] = a;
            rcount = i + 1;
        }
#pragma unroll
        for (int i = 0; i < 5; i++) {
            float a = (i < rcount) ? accv[i] : 0.f;
            a += __shfl_down_sync(0xffffffffu, a, 16);
            a += __shfl_down_sync(0xffffffffu, a, 8);
            a += __shfl_down_sync(0xffffffffu, a, 4);
            a += __shfl_down_sync(0xffffffffu, a, 2);
            a += __shfl_down_sync(0xffffffffu, a, 1);
            accv[i] = a;
        }

        // per-warp online softmax stats on lane 0
        if (lane == 0) {
            float m = -INFINITY, s = 0.f;
            int a = 0x7fffffff;
#pragma unroll
            for (int i = 0; i < 5; i++) {
                if (i < rcount) {
                    int lr = warp + NWARP * i;
                    float l = accv[i] + s_bo[lr];
                    if (l > m) { s = s * __expf(m - l) + 1.f; m = l; a = r0 + lr; }
                    else       { s += __expf(l - m); }
                }
            }
            s_wm[warp] = m; s_wa[warp] = a; s_ws[warp] = s;
        }
        __syncthreads();

        // warp0: merge 16 warp triples, publish block partial
        if (warp == 0) {
            float mo = (lane < NWARP) ? s_wm[lane] : -INFINITY;
            float so = (lane < NWARP) ? s_ws[lane] : 0.f;
            int   ao = (lane < NWARP) ? s_wa[lane] : 0x7fffffff;
            float m = mo; int a = ao;
#pragma unroll
            for (int off = 16; off; off >>= 1) {
                float m2 = __shfl_xor_sync(0xffffffffu, m, off);
                int   a2 = __shfl_xor_sync(0xffffffffu, a, off);
                if (m2 > m || (m2 == m && a2 < a)) { m = m2; a = a2; }
            }
            float sc = (lane < NWARP) ? so * __expf(mo - m) : 0.f;
#pragma unroll
            for (int off = 16; off; off >>= 1)
                sc += __shfl_xor_sync(0xffffffffu, sc, off);
            if (lane == 0) {
                g_pm[par][b] = m;
                g_pa[par][b] = a;
                g_ps[par][b] = sc;
                red_release(&g_cp);
            }
        }

        // ===== wait partials, redundant global merge =====
        if (tid == 0) {
            unsigned tgt = (unsigned)NB * (unsigned)(t + 1);
            while (ld_acquire(&g_cp) < tgt) {}
        }
        __syncthreads();

        if (warp == 0) {
            float mi[5], si[5]; int ai[5];
#pragma unroll
            for (int i = 0; i < 5; i++) {
                int idx = lane + 32 * i;
                bool v = idx < NB;
                mi[i] = v ? __ldcv(&g_pm[par][idx]) : -INFINITY;
                ai[i] = v ? __ldcv(&g_pa[par][idx]) : 0x7fffffff;
                si[i] = v ? __ldcv(&g_ps[par][idx]) : 0.f;
            }
            float m = mi[0]; int a = ai[0];
#pragma unroll
            for (int i = 1; i < 5; i++)
                if (mi[i] > m || (mi[i] == m && ai[i] < a)) { m = mi[i]; a = ai[i]; }
#pragma unroll
            for (int off = 16; off; off >>= 1) {
                float m2 = __shfl_xor_sync(0xffffffffu, m, off);
                int   a2 = __shfl_xor_sync(0xffffffffu, a, off);
                if (m2 > m || (m2 == m && a2 < a)) { m = m2; a = a2; }
            }
            float sc = 0.f;
#pragma unroll
            for (int i = 0; i < 5; i++) sc += si[i] * __expf(mi[i] - m);
#pragma unroll
            for (int off = 16; off; off >>= 1)
                sc += __shfl_xor_sync(0xffffffffu, sc, off);
            if (lane == 0) {
                s_bc[0] = __int_as_float(a);
                s_bc[1] = -__logf(sc);
            }
        }
        __syncthreads();

        const int   pred    = __float_as_int(s_bc[0]);
        const float logp    = s_bc[1];
        const bool  emitted = (pred != 0);

        if (b == 0 && tid == 0) {
            if (t < out_size) out[t] = emitted ? (float)pred : 0.0f;
            if (emitted) score += logp;
        }

        // ===== LSTM update (uniform branch per block) =====
        if (emitted) {
            if (tid < DUNITS / 4)
                ((float4*)s_ey)[tid] =
                    __ldg(((const float4*)(embed + (size_t)pred * DUNITS)) + tid);
            __syncthreads();

            for (int lr = warp; lr < 4 * nk; lr += NWARP) {
                const float4* r4 = (const float4*)(sWih + lr * DUNITS);
                const float4* e4 = (const float4*)s_ey;
                float acc = 0.f;
#pragma unroll
                for (int q = 0; q < 4; q++) {
                    float4 w = r4[lane + 32 * q], ev = e4[lane + 32 * q];
                    acc += w.x * ev.x + w.y * ev.y + w.z * ev.z + w.w * ev.w;
                }
                for (int off = 16; off; off >>= 1)
                    acc += __shfl_down_sync(0xffffffffu, acc, off);
                if (lane == 0) s_gt[lr] = s_bs[lr] + s_gh[lr] + acc;
            }
            __syncthreads();
        }

        if (tid < nk) {
            float yv;
            if (emitted) {
                float gi_ = s_gt[4 * tid + 0], gf_ = s_gt[4 * tid + 1];
                float gg_ = s_gt[4 * tid + 2], go_ = s_gt[4 * tid + 3];
                float c  = s_c[tid];
                float cn = sigm(gf_) * c + sigm(gi_) * tanhf(gg_);
                yv = sigm(go_) * tanhf(cn);
                s_c[tid]  = cn;
                s_my[tid] = yv;
            } else {
                yv = s_my[tid];
            }
            g_y[par ^ 1][k0 + tid] = yv;
            red_release(&g_cy);
        }
    }

    if (b == 0) {
        if (tid == 0 && out_size > T_FRAMES) out[T_FRAMES] = score;
        for (int i = T_FRAMES + 1 + tid; i < out_size; i += NT) out[i] = 0.f;
    }
}

// ---------------- launch ----------------
extern "C" void kernel_launch(void* const* d_in, const int* in_sizes, int n_in,
                              void* d_out, int out_size) {
    (void)in_sizes; (void)n_in;
    const float* h     = (const float*)d_in[0];
    const float* embed = (const float*)d_in[1];
    const float* Wih   = (const float*)d_in[2];
    const float* Whh   = (const float*)d_in[3];
    const float* bih   = (const float*)d_in[4];
    const float* bhh   = (const float*)d_in[5];
    const float* Wenc  = (const float*)d_in[6];
    const float* benc  = (const float*)d_in[7];
    const float* Wdec  = (const float*)d_in[8];
    const float* Wout  = (const float*)d_in[9];
    const float* bout  = (const float*)d_in[10];
    float* out = (float*)d_out;

    const int smem_bytes = SM_TOTAL_FLOATS * (int)sizeof(float);
    cudaFuncSetAttribute(decode_kernel,
                         cudaFuncAttributeMaxDynamicSharedMemorySize, smem_bytes);

    hp_kernel<<<T_FRAMES / 8, 256>>>(h, Wenc, benc);
    decode_kernel<<<NB, NT, smem_bytes>>>(embed, Wih, Whh, bih, bhh,
                                          Wdec, Wout, bout, out, out_size);
}

// round 4
// speedup vs baseline: 1.6087x; 1.5065x over previous
#include <cuda_runtime.h>
#include <math.h>
#include <stdint.h>

#define T_FRAMES 2048
#define EPROJS   1024
#define DUNITS   512
#define JOINT    512
#define ODIM     10000
#define NB       148
#define NT       512
#define NWARP    (NT / 32)

// ---------------- global scratch ----------------
__device__ float  g_hp[T_FRAMES * JOINT];     // encoder-side joint projection
__device__ float  g_y[2][DUNITS];             // double-buffered prediction-net state
__device__ float  g_z[2][JOINT];              // double-buffered joint hidden
__device__ float4 g_part[2][NB];              // packed (max, sumexp, argmax-bits, _)
__device__ __align__(128) unsigned g_cy;      // y arrivals   (NB per step)
__device__ __align__(128) unsigned g_cz;      // z arrivals   (NB per step)
__device__ __align__(128) unsigned g_cp;      // partial arrivals (NB per step)

__device__ __forceinline__ void red_release(unsigned* p) {
    asm volatile("red.release.gpu.global.add.u32 [%0], 1;" :: "l"(p) : "memory");
}
__device__ __forceinline__ unsigned ld_acquire(unsigned* p) {
    unsigned v;
    asm volatile("ld.acquire.gpu.global.u32 %0, [%1];" : "=r"(v) : "l"(p) : "memory");
    return v;
}
__device__ __forceinline__ float sigm(float x) { return 1.f / (1.f + expf(-x)); }

// ---------------- hp = h @ W_enc^T + b_enc ----------------
__global__ void hp_kernel(const float* __restrict__ h,
                          const float* __restrict__ Wenc,
                          const float* __restrict__ benc) {
    if (blockIdx.x == 0 && threadIdx.x == 0) { g_cy = 0u; g_cz = 0u; g_cp = 0u; }

    __shared__ float sh[8 * EPROJS];
    const int tid  = threadIdx.x;
    const int warp = tid >> 5;
    const int lane = tid & 31;
    const size_t t0 = (size_t)blockIdx.x * 8;

    const float4* hsrc = (const float4*)(h + t0 * EPROJS);
    float4* sh4 = (float4*)sh;
    for (int i = tid; i < 8 * EPROJS / 4; i += 256) sh4[i] = hsrc[i];
    __syncthreads();

    const float4* w0 = (const float4*)Wenc;
    for (int pass = 0; pass < 16; pass++) {
        int jb = (pass * 8 + warp) * 4;
        float acc[8][4];
#pragma unroll
        for (int tt = 0; tt < 8; tt++)
#pragma unroll
            for (int jj = 0; jj < 4; jj++) acc[tt][jj] = 0.f;

        for (int qq = 0; qq < 8; qq++) {
            int q = qq * 32 + lane;
            float4 w[4];
#pragma unroll
            for (int jj = 0; jj < 4; jj++)
                w[jj] = w0[(size_t)(jb + jj) * (EPROJS / 4) + q];
#pragma unroll
            for (int tt = 0; tt < 8; tt++) {
                float4 hv = sh4[tt * (EPROJS / 4) + q];
#pragma unroll
                for (int jj = 0; jj < 4; jj++)
                    acc[tt][jj] += hv.x * w[jj].x + hv.y * w[jj].y +
                                   hv.z * w[jj].z + hv.w * w[jj].w;
            }
        }
#pragma unroll
        for (int tt = 0; tt < 8; tt++) {
#pragma unroll
            for (int jj = 0; jj < 4; jj++) {
                float v = acc[tt][jj];
                for (int off = 16; off; off >>= 1)
                    v += __shfl_down_sync(0xffffffffu, v, off);
                if (lane == 0)
                    g_hp[(t0 + tt) * JOINT + jb + jj] = v + benc[jb + jj];
            }
        }
    }
}

// ---------------- smem layout (floats) ----------------
#define SM_WOUT   0
#define SM_WHH    (SM_WOUT + 68 * JOINT)
#define SM_WIH    (SM_WHH + 16 * DUNITS)
#define SM_WDEC   (SM_WIH + 16 * DUNITS)
#define SM_Y      (SM_WDEC + 4 * DUNITS)
#define SM_Z      (SM_Y + DUNITS)
#define SM_EY     (SM_Z + JOINT)
#define SM_BO     (SM_EY + DUNITS)
#define SM_GH     (SM_BO + 96)
#define SM_GT     (SM_GH + 16)
#define SM_BS     (SM_GT + 16)
#define SM_C      (SM_BS + 16)
#define SM_MY     (SM_C + 4)
#define SM_BC     (SM_MY + 4)
#define SM_WM     (SM_BC + 8)
#define SM_WA     (SM_WM + NWARP)
#define SM_WS     (SM_WA + NWARP)
#define SM_TOTAL_FLOATS (SM_WS + NWARP)

__global__ void __launch_bounds__(NT, 1)
decode_kernel(const float* __restrict__ embed,
              const float* __restrict__ Wih, const float* __restrict__ Whh,
              const float* __restrict__ bih, const float* __restrict__ bhh,
              const float* __restrict__ Wdec, const float* __restrict__ Wout,
              const float* __restrict__ bout,
              float* __restrict__ out, int out_size) {
    extern __shared__ float sm[];
    const int b    = blockIdx.x;
    const int tid  = threadIdx.x;
    const int warp = tid >> 5;
    const int lane = tid & 31;

    const int r0 = (b * ODIM) / NB, r1 = ((b + 1) * ODIM) / NB, nr = r1 - r0;
    const int k0 = (b * DUNITS) / NB, k1 = ((b + 1) * DUNITS) / NB, nk = k1 - k0;

    float* sWout = sm + SM_WOUT;
    float* sWhh  = sm + SM_WHH;
    float* sWih  = sm + SM_WIH;
    float* sWdec = sm + SM_WDEC;
    float* s_y   = sm + SM_Y;
    float* s_z   = sm + SM_Z;
    float* s_ey  = sm + SM_EY;
    float* s_bo  = sm + SM_BO;
    float* s_gh  = sm + SM_GH;
    float* s_gt  = sm + SM_GT;
    float* s_bs  = sm + SM_BS;
    float* s_c   = sm + SM_C;
    float* s_my  = sm + SM_MY;
    float* s_bc  = sm + SM_BC;
    float* s_wm  = sm + SM_WM;
    int*   s_wa  = (int*)(sm + SM_WA);
    float* s_ws  = sm + SM_WS;

    // ---- load weights into shared (resident for entire decode) ----
    {
        const float4* src = (const float4*)(Wout + (size_t)r0 * JOINT);
        float4* dst = (float4*)sWout;
        for (int i = tid; i < nr * (JOINT / 4); i += NT) dst[i] = src[i];
    }
    for (int i = tid; i < nr; i += NT) s_bo[i] = bout[r0 + i];
    {
        const int ng = 4 * nk;
        for (int i = tid; i < ng * (DUNITS / 4); i += NT) {
            int lr = i / (DUNITS / 4), x = i % (DUNITS / 4);
            int gi = lr & 3, ki = lr >> 2;
            size_t G = (size_t)(gi * DUNITS + k0 + ki);
            ((float4*)sWhh)[i] = ((const float4*)(Whh + G * DUNITS))[x];
            ((float4*)sWih)[i] = ((const float4*)(Wih + G * DUNITS))[x];
        }
        for (int i = tid; i < ng; i += NT) {
            int gi = i & 3, ki = i >> 2;
            int G = gi * DUNITS + k0 + ki;
            s_bs[i] = bih[G] + bhh[G];
        }
    }
    {
        const float4* src = (const float4*)(Wdec + (size_t)k0 * DUNITS);
        float4* dst = (float4*)sWdec;
        for (int i = tid; i < nk * (DUNITS / 4); i += NT) dst[i] = src[i];
    }
    __syncthreads();

    // ---- prologue: y0 from zero input / zero state (gates = biases) ----
    if (warp == 0) {
        if (lane < nk) {
            float gi_ = s_bs[4 * lane + 0];
            float gg_ = s_bs[4 * lane + 2];
            float go_ = s_bs[4 * lane + 3];
            float c  = sigm(gi_) * tanhf(gg_);
            float yv = sigm(go_) * tanhf(c);
            s_c[lane]  = c;
            s_my[lane] = yv;
            g_y[0][k0 + lane] = yv;
        }
        __syncwarp();
        if (lane == 0) red_release(&g_cy);           // ONE release per block
    }

    float score = 0.f;

    for (int t = 0; t < T_FRAMES; t++) {
        const int par = t & 1;

        // ===== wait y(t) (NB block-arrivals), stage =====
        if (tid == 0) {
            const unsigned tgt = (unsigned)NB * (unsigned)(t + 1);
            while (ld_acquire(&g_cy) < tgt) {}
        }
        __syncthreads();
        if (tid < DUNITS / 4)
            ((float4*)s_y)[tid] = __ldcv(((const float4*)g_y[par]) + tid);
        __syncthreads();

        // ===== z rows on warps 0..nk-1, single release via named barrier =====
        if (warp < nk) {
            const float4* r4 = (const float4*)(sWdec + warp * DUNITS);
            const float4* y4 = (const float4*)s_y;
            float acc = 0.f;
#pragma unroll
            for (int q = 0; q < 4; q++) {
                float4 w = r4[lane + 32 * q], yv = y4[lane + 32 * q];
                acc += w.x * yv.x + w.y * yv.y + w.z * yv.z + w.w * yv.w;
            }
            for (int off = 16; off; off >>= 1)
                acc += __shfl_down_sync(0xffffffffu, acc, off);
            if (lane == 0) {
                float zv = tanhf(__ldg(&g_hp[(size_t)t * JOINT + k0 + warp]) + acc);
                g_z[par][k0 + warp] = zv;
            }
            asm volatile("bar.sync 1, %0;" :: "r"(nk * 32) : "memory");
            if (warp == 0 && lane == 0) red_release(&g_cz);   // ONE release
        }

        // ===== gh rows on all warps (overlaps z-wait of other blocks) =====
        for (int g = warp; g < 4 * nk; g += NWARP) {
            const float4* r4 = (const float4*)(sWhh + g * DUNITS);
            const float4* y4 = (const float4*)s_y;
            float acc = 0.f;
#pragma unroll
            for (int q = 0; q < 4; q++) {
                float4 w = r4[lane + 32 * q], yv = y4[lane + 32 * q];
                acc += w.x * yv.x + w.y * yv.y + w.z * yv.z + w.w * yv.w;
            }
            for (int off = 16; off; off >>= 1)
                acc += __shfl_down_sync(0xffffffffu, acc, off);
            if (lane == 0) s_gh[g] = acc;
        }

        // ===== wait z(t), stage to regs =====
        if (tid == 0) {
            const unsigned tgt = (unsigned)NB * (unsigned)(t + 1);
            while (ld_acquire(&g_cz) < tgt) {}
        }
        __syncthreads();
        if (tid < JOINT / 4)
            ((float4*)s_z)[tid] = __ldcv(((const float4*)g_z[par]) + tid);
        __syncthreads();

        float4 zr[4];
#pragma unroll
        for (int q = 0; q < 4; q++) zr[q] = ((const float4*)s_z)[lane + 32 * q];

        // ===== logits rows: batched dots, batched shuffle reduces =====
        float accv[5];
        int rcount = 0;
        for (int lr = warp, i = 0; lr < nr; lr += NWARP, i++) {
            const float4* r4 = (const float4*)(sWout + lr * JOINT);
            float a = 0.f;
#pragma unroll
            for (int q = 0; q < 4; q++) {
                float4 w = r4[lane + 32 * q];
                a += w.x * zr[q].x + w.y * zr[q].y + w.z * zr[q].z + w.w * zr[q].w;
            }
            accv[i] = a;
            rcount = i + 1;
        }
#pragma unroll
        for (int i = 0; i < 5; i++) {
            float a = (i < rcount) ? accv[i] : 0.f;
            a += __shfl_down_sync(0xffffffffu, a, 16);
            a += __shfl_down_sync(0xffffffffu, a, 8);
            a += __shfl_down_sync(0xffffffffu, a, 4);
            a += __shfl_down_sync(0xffffffffu, a, 2);
            a += __shfl_down_sync(0xffffffffu, a, 1);
            accv[i] = a;
        }

        // per-warp online softmax stats on lane 0
        if (lane == 0) {
            float m = -INFINITY, s = 0.f;
            int a = 0x7fffffff;
#pragma unroll
            for (int i = 0; i < 5; i++) {
                if (i < rcount) {
                    int lr = warp + NWARP * i;
                    float l = accv[i] + s_bo[lr];
                    if (l > m) { s = s * __expf(m - l) + 1.f; m = l; a = r0 + lr; }
                    else       { s += __expf(l - m); }
                }
            }
            s_wm[warp] = m; s_wa[warp] = a; s_ws[warp] = s;
        }
        __syncthreads();

        // warp0: merge 16 warp triples, publish block partial (packed float4)
        if (warp == 0) {
            float mo = (lane < NWARP) ? s_wm[lane] : -INFINITY;
            float so = (lane < NWARP) ? s_ws[lane] : 0.f;
            int   ao = (lane < NWARP) ? s_wa[lane] : 0x7fffffff;
            float m = mo; int a = ao;
#pragma unroll
            for (int off = 16; off; off >>= 1) {
                float m2 = __shfl_xor_sync(0xffffffffu, m, off);
                int   a2 = __shfl_xor_sync(0xffffffffu, a, off);
                if (m2 > m || (m2 == m && a2 < a)) { m = m2; a = a2; }
            }
            float sc = (lane < NWARP) ? so * __expf(mo - m) : 0.f;
#pragma unroll
            for (int off = 16; off; off >>= 1)
                sc += __shfl_xor_sync(0xffffffffu, sc, off);
            if (lane == 0) {
                g_part[par][b] = make_float4(m, sc, __int_as_float(a), 0.f);
                red_release(&g_cp);
            }
        }

        // ===== wait partials, redundant global merge =====
        if (tid == 0) {
            const unsigned tgt = (unsigned)NB * (unsigned)(t + 1);
            while (ld_acquire(&g_cp) < tgt) {}
        }
        __syncthreads();

        if (warp == 0) {
            float mi[5], si[5]; int ai[5];
#pragma unroll
            for (int i = 0; i < 5; i++) {
                int idx = lane + 32 * i;
                if (idx < NB) {
                    float4 p = __ldcv(&g_part[par][idx]);
                    mi[i] = p.x; si[i] = p.y; ai[i] = __float_as_int(p.z);
                } else { mi[i] = -INFINITY; si[i] = 0.f; ai[i] = 0x7fffffff; }
            }
            float m = mi[0]; int a = ai[0];
#pragma unroll
            for (int i = 1; i < 5; i++)
                if (mi[i] > m || (mi[i] == m && ai[i] < a)) { m = mi[i]; a = ai[i]; }
#pragma unroll
            for (int off = 16; off; off >>= 1) {
                float m2 = __shfl_xor_sync(0xffffffffu, m, off);
                int   a2 = __shfl_xor_sync(0xffffffffu, a, off);
                if (m2 > m || (m2 == m && a2 < a)) { m = m2; a = a2; }
            }
            float sc = 0.f;
#pragma unroll
            for (int i = 0; i < 5; i++) sc += si[i] * __expf(mi[i] - m);
#pragma unroll
            for (int off = 16; off; off >>= 1)
                sc += __shfl_xor_sync(0xffffffffu, sc, off);
            if (lane == 0) {
                s_bc[0] = __int_as_float(a);
                s_bc[1] = -__logf(sc);
            }
        }
        __syncthreads();

        const int   pred    = __float_as_int(s_bc[0]);
        const float logp    = s_bc[1];
        const bool  emitted = (pred != 0);

        if (b == 0 && tid == 0) {
            if (t < out_size) out[t] = emitted ? (float)pred : 0.0f;
            if (emitted) score += logp;
        }

        // ===== LSTM update (uniform branch per block) =====
        if (emitted) {
            if (tid < DUNITS / 4)
                ((float4*)s_ey)[tid] =
                    __ldg(((const float4*)(embed + (size_t)pred * DUNITS)) + tid);
            __syncthreads();

            for (int lr = warp; lr < 4 * nk; lr += NWARP) {
                const float4* r4 = (const float4*)(sWih + lr * DUNITS);
                const float4* e4 = (const float4*)s_ey;
                float acc = 0.f;
#pragma unroll
                for (int q = 0; q < 4; q++) {
                    float4 w = r4[lane + 32 * q], ev = e4[lane + 32 * q];
                    acc += w.x * ev.x + w.y * ev.y + w.z * ev.z + w.w * ev.w;
                }
                for (int off = 16; off; off >>= 1)
                    acc += __shfl_down_sync(0xffffffffu, acc, off);
                if (lane == 0) s_gt[lr] = s_bs[lr] + s_gh[lr] + acc;
            }
            __syncthreads();
        }

        if (warp == 0) {
            if (lane < nk) {
                float yv;
                if (emitted) {
                    float gi_ = s_gt[4 * lane + 0], gf_ = s_gt[4 * lane + 1];
                    float gg_ = s_gt[4 * lane + 2], go_ = s_gt[4 * lane + 3];
                    float c  = s_c[lane];
                    float cn = sigm(gf_) * c + sigm(gi_) * tanhf(gg_);
                    yv = sigm(go_) * tanhf(cn);
                    s_c[lane]  = cn;
                    s_my[lane] = yv;
                } else {
                    yv = s_my[lane];
                }
                g_y[par ^ 1][k0 + lane] = yv;
            }
            __syncwarp();
            if (lane == 0) red_release(&g_cy);       // ONE release per block
        }
    }

    if (b == 0) {
        if (tid == 0 && out_size > T_FRAMES) out[T_FRAMES] = score;
        for (int i = T_FRAMES + 1 + tid; i < out_size; i += NT) out[i] = 0.f;
    }
}

// ---------------- launch ----------------
extern "C" void kernel_launch(void* const* d_in, const int* in_sizes, int n_in,
                              void* d_out, int out_size) {
    (void)in_sizes; (void)n_in;
    const float* h     = (const float*)d_in[0];
    const float* embed = (const float*)d_in[1];
    const float* Wih   = (const float*)d_in[2];
    const float* Whh   = (const float*)d_in[3];
    const float* bih   = (const float*)d_in[4];
    const float* bhh   = (const float*)d_in[5];
    const float* Wenc  = (const float*)d_in[6];
    const float* benc  = (const float*)d_in[7];
    const float* Wdec  = (const float*)d_in[8];
    const float* Wout  = (const float*)d_in[9];
    const float* bout  = (const float*)d_in[10];
    float* out = (float*)d_out;

    const int smem_bytes = SM_TOTAL_FLOATS * (int)sizeof(float);
    cudaFuncSetAttribute(decode_kernel,
                         cudaFuncAttributeMaxDynamicSharedMemorySize, smem_bytes);

    hp_kernel<<<T_FRAMES / 8, 256>>>(h, Wenc, benc);
    decode_kernel<<<NB, NT, smem_bytes>>>(embed, Wih, Whh, bih, bhh,
                                          Wdec, Wout, bout, out, out_size);
}